// round 10
// baseline (speedup 1.0000x reference)
#include <cuda_runtime.h>
#include <cuda_fp16.h>

#define N_USERS 100000
#define N_ITEMS 50000
#define N_NODES 150000           // N_USERS + N_ITEMS
#define NNZ_E 4800000
#define BATCH 16384
#define ROW_CAP 96               // padded slots per row; P(deg>96) ~ 1e-20 at mean 32

// ---------------- scratch (device globals; no allocation allowed) -----------
// fp16 embedding buffers, one per layer: 8 uint4 (=64 halfs =128B) per row
__device__ uint4 g_e0[N_NODES * 8];              // 19.2 MB (fp16 of inputs)
__device__ uint4 g_e1[N_NODES * 8];              // 19.2 MB (layer 1)
__device__ uint4 g_e2[N_NODES * 8];              // 19.2 MB (layer 2)
__device__ uint4 g_e3[N_NODES * 8];              // 19.2 MB (layer 3)
__device__ int   g_fill[N_NODES];
// padded bins, 2 edges per int4: {col0, val0_h2, col1, val1_h2}; val stored as half2{v,v}
__device__ int4  g_pedge4[N_NODES * ROW_CAP / 2];   // 115.2 MB
__device__ int   g_is64;

// ---------------- fused prep: zero fill + fp16 init + idx-width detect ------
__global__ void k_prep(const float2* __restrict__ ue2, const float2* __restrict__ ie2,
                       const int* __restrict__ uidx_i) {
    int i = blockIdx.x * blockDim.x + threadIdx.x;   // over N_NODES * 32 half2
    if (i >= N_NODES * 32) return;
    int node = i >> 5;
    int c    = i & 31;
    float2 f = (node < N_USERS) ? ue2[node * 32 + c]
                                : ie2[(node - N_USERS) * 32 + c];
    half2 h = __float22half2_rn(f);
    ((unsigned*)g_e0)[i] = *(unsigned*)&h;

    if (i < N_NODES) g_fill[i] = 0;

    if (i == 0) {
        // int64 indices (< 2^31) => every odd 32-bit word is 0.
        int all0 = 1;
        #pragma unroll
        for (int k = 1; k < 64; k += 2) if (uidx_i[k] != 0) all0 = 0;
        g_is64 = all0;
    }
}

// ---------------- scatter into padded bins (val pre-converted to half2) ------
__device__ __forceinline__ int val2h2(float v) {
    half hv = __float2half_rn(v);
    half2 d = __half2half2(hv);
    return *(int*)&d;
}

__global__ void k_scatter(const int4* __restrict__ rows4, const int4* __restrict__ cols4,
                          const float4* __restrict__ vals4) {
    int i = blockIdx.x * blockDim.x + threadIdx.x;   // over NNZ_E/4
    if (i >= NNZ_E / 4) return;
    int4   r = rows4[i];
    int4   c = cols4[i];
    float4 v = vals4[i];
    int2* pedge2 = (int2*)g_pedge4;
    int s;
    s = atomicAdd(&g_fill[r.x], 1); pedge2[r.x * ROW_CAP + s] = make_int2(c.x, val2h2(v.x));
    s = atomicAdd(&g_fill[r.y], 1); pedge2[r.y * ROW_CAP + s] = make_int2(c.y, val2h2(v.y));
    s = atomicAdd(&g_fill[r.z], 1); pedge2[r.z * ROW_CAP + s] = make_int2(c.z, val2h2(v.z));
    s = atomicAdd(&g_fill[r.w], 1); pedge2[r.w * ROW_CAP + s] = make_int2(c.w, val2h2(v.w));
}

// ---------------- SpMM: quarter-warp per row, HFMA2 partials -----------------
__device__ __forceinline__ void acc_h(half2& p0, half2& p1, half2& p2, half2& p3,
                                      uint4 x, int vbits) {
    half2 vv = *(half2*)&vbits;
    p0 = __hfma2(*(half2*)&x.x, vv, p0);
    p1 = __hfma2(*(half2*)&x.y, vv, p1);
    p2 = __hfma2(*(half2*)&x.z, vv, p2);
    p3 = __hfma2(*(half2*)&x.w, vv, p3);
}

__device__ __forceinline__ void flush_h(float2& A0, float2& A1, float2& A2, float2& A3,
                                        half2 p0, half2 p1, half2 p2, half2 p3) {
    float2 f;
    f = __half22float2(p0); A0.x += f.x; A0.y += f.y;
    f = __half22float2(p1); A1.x += f.x; A1.y += f.y;
    f = __half22float2(p2); A2.x += f.x; A2.y += f.y;
    f = __half22float2(p3); A3.x += f.x; A3.y += f.y;
}

__global__ void __launch_bounds__(256) k_spmm(int layer) {
    const uint4* __restrict__ src;
    uint4*       __restrict__ dst;
    if (layer == 0)      { src = g_e0; dst = g_e1; }
    else if (layer == 1) { src = g_e1; dst = g_e2; }
    else                 { src = g_e2; dst = g_e3; }

    int t    = blockIdx.x * blockDim.x + threadIdx.x;
    int w    = t >> 5;
    int lane = t & 31;
    int row  = w * 4 + (lane >> 3);       // 4 rows per warp (4 indep chains)
    int ql   = lane & 7;                  // lane within quarter-warp
    if (row >= N_NODES) return;

    const int4* __restrict__ ep4 = &g_pedge4[row * (ROW_CAP / 2)];
    int n = __ldg(&g_fill[row]);
    if (n > ROW_CAP) n = ROW_CAP;

    float2 A0 = {0.f, 0.f}, A1 = {0.f, 0.f}, A2 = {0.f, 0.f}, A3 = {0.f, 0.f};
    const half2 hz = __float2half2_rn(0.f);

    int j = 0;
    for (; j + 7 < n; j += 8) {
        int4 E0 = __ldg(&ep4[(j >> 1)]);
        int4 E1 = __ldg(&ep4[(j >> 1) + 1]);
        int4 E2 = __ldg(&ep4[(j >> 1) + 2]);
        int4 E3 = __ldg(&ep4[(j >> 1) + 3]);
        uint4 x0 = __ldg(&src[E0.x * 8 + ql]);
        uint4 x1 = __ldg(&src[E0.z * 8 + ql]);
        uint4 x2 = __ldg(&src[E1.x * 8 + ql]);
        uint4 x3 = __ldg(&src[E1.z * 8 + ql]);
        uint4 x4 = __ldg(&src[E2.x * 8 + ql]);
        uint4 x5 = __ldg(&src[E2.z * 8 + ql]);
        uint4 x6 = __ldg(&src[E3.x * 8 + ql]);
        uint4 x7 = __ldg(&src[E3.z * 8 + ql]);
        half2 p0 = hz, p1 = hz, p2 = hz, p3 = hz;
        acc_h(p0, p1, p2, p3, x0, E0.y);
        acc_h(p0, p1, p2, p3, x1, E0.w);
        acc_h(p0, p1, p2, p3, x2, E1.y);
        acc_h(p0, p1, p2, p3, x3, E1.w);
        acc_h(p0, p1, p2, p3, x4, E2.y);
        acc_h(p0, p1, p2, p3, x5, E2.w);
        acc_h(p0, p1, p2, p3, x6, E3.y);
        acc_h(p0, p1, p2, p3, x7, E3.w);
        flush_h(A0, A1, A2, A3, p0, p1, p2, p3);
    }
    if (j < n) {
        const int2* __restrict__ ep2 = (const int2*)ep4;
        half2 p0 = hz, p1 = hz, p2 = hz, p3 = hz;
        for (; j < n; j++) {
            int2 e = __ldg(&ep2[j]);
            uint4 x = __ldg(&src[e.x * 8 + ql]);
            acc_h(p0, p1, p2, p3, x, e.y);
        }
        flush_h(A0, A1, A2, A3, p0, p1, p2, p3);
    }

    half2 h0 = __float22half2_rn(A0);
    half2 h1 = __float22half2_rn(A1);
    half2 h2 = __float22half2_rn(A2);
    half2 h3 = __float22half2_rn(A3);
    uint4 hv;
    hv.x = *(unsigned*)&h0; hv.y = *(unsigned*)&h1;
    hv.z = *(unsigned*)&h2; hv.w = *(unsigned*)&h3;
    dst[row * 8 + ql] = hv;
}

// ---------------- epilogue: sum 4 layer embeddings at gathered rows, dot -----
__global__ void k_dot(const float2* __restrict__ ue2, const float2* __restrict__ ie2,
                      const void* __restrict__ uidx_raw, const void* __restrict__ iidx_raw,
                      float* __restrict__ out) {
    int t    = blockIdx.x * blockDim.x + threadIdx.x;
    int w    = t >> 5;
    int lane = t & 31;
    if (w >= BATCH) return;

    long long u, it;
    if (g_is64) {
        u  = ((const long long*)uidx_raw)[w];
        it = ((const long long*)iidx_raw)[w];
    } else {
        u  = ((const int*)uidx_raw)[w];
        it = ((const int*)iidx_raw)[w];
    }

    size_t un = (size_t)u;                       // user node id
    size_t in = (size_t)N_USERS + (size_t)it;    // item node id

    // layer 0 straight from the inputs (exact fp32)
    float2 x = ue2[un * 32 + lane];
    float2 y = ie2[(size_t)it * 32 + lane];

    const unsigned* layers[3] = { (const unsigned*)g_e1, (const unsigned*)g_e2,
                                  (const unsigned*)g_e3 };
    #pragma unroll
    for (int l = 0; l < 3; l++) {
        unsigned hx = __ldg(&layers[l][un * 32 + lane]);
        unsigned hy = __ldg(&layers[l][in * 32 + lane]);
        float2 fx = __half22float2(*(half2*)&hx);
        float2 fy = __half22float2(*(half2*)&hy);
        x.x += fx.x; x.y += fx.y;
        y.x += fy.x; y.y += fy.y;
    }

    float p = x.x * y.x + x.y * y.y;
    #pragma unroll
    for (int off = 16; off; off >>= 1)
        p += __shfl_xor_sync(0xffffffffu, p, off);
    if (lane == 0) out[w] = p * (1.0f / 16.0f);   // (sum/4)·(sum/4)
}

// ---------------- launch ------------------------------------------------------
extern "C" void kernel_launch(void* const* d_in, const int* in_sizes, int n_in,
                              void* d_out, int out_size) {
    const float*  ue   = (const float*)d_in[0];
    const float*  ie   = (const float*)d_in[1];
    const int*    rows = (const int*)d_in[2];
    const int*    cols = (const int*)d_in[3];
    const float*  vals = (const float*)d_in[4];
    const void*   uidx = d_in[5];
    const void*   iidx = d_in[6];
    float* out = (float*)d_out;

    k_prep<<<(N_NODES * 32 + 255) / 256, 256>>>((const float2*)ue, (const float2*)ie,
                                                (const int*)uidx);
    k_scatter<<<(NNZ_E / 4 + 255) / 256, 256>>>((const int4*)rows, (const int4*)cols,
                                                (const float4*)vals);

    int spmm_blocks = ((N_NODES + 3) / 4 * 32 + 255) / 256;  // quarter-warp per row
    k_spmm<<<spmm_blocks, 256>>>(0);
    k_spmm<<<spmm_blocks, 256>>>(1);
    k_spmm<<<spmm_blocks, 256>>>(2);

    k_dot<<<BATCH * 32 / 256, 256>>>((const float2*)ue, (const float2*)ie, uidx, iidx, out);
}

// round 12
// speedup vs baseline: 1.0584x; 1.0584x over previous
#include <cuda_runtime.h>
#include <cuda_fp16.h>

#define N_USERS 100000
#define N_ITEMS 50000
#define N_NODES 150000           // N_USERS + N_ITEMS
#define NNZ_E 4800000
#define BATCH 16384
#define ROW_CAP 96               // padded slots per row; P(deg>96) ~ 1e-20 at mean 32

// ---------------- scratch (device globals; no allocation allowed) -----------
// fp16 embedding buffers, one per layer: 8 uint4 (=64 halfs =128B) per row
__device__ uint4 g_e0[N_NODES * 8];              // 19.2 MB (fp16 of inputs)
__device__ uint4 g_e1[N_NODES * 8];              // 19.2 MB (layer 1)
__device__ uint4 g_e2[N_NODES * 8];              // 19.2 MB (layer 2)
__device__ uint4 g_e3[N_NODES * 8];              // 19.2 MB (layer 3)
__device__ int   g_fill[N_NODES];
// padded bins, 2 edges per int4: {col0, val0_f32bits, col1, val1_f32bits}
__device__ int4  g_pedge4[N_NODES * ROW_CAP / 2];   // 115.2 MB
__device__ int   g_is64;

// ---------------- fused prep: zero fill + fp16 init + idx-width detect ------
__global__ void k_prep(const float2* __restrict__ ue2, const float2* __restrict__ ie2,
                       const int* __restrict__ uidx_i) {
    int i = blockIdx.x * blockDim.x + threadIdx.x;   // over N_NODES * 32 half2
    if (i >= N_NODES * 32) return;
    int node = i >> 5;
    int c    = i & 31;
    float2 f = (node < N_USERS) ? ue2[node * 32 + c]
                                : ie2[(node - N_USERS) * 32 + c];
    half2 h = __float22half2_rn(f);
    ((unsigned*)g_e0)[i] = *(unsigned*)&h;

    if (i < N_NODES) g_fill[i] = 0;

    if (i == 0) {
        // int64 indices (< 2^31) => every odd 32-bit word is 0.
        int all0 = 1;
        #pragma unroll
        for (int k = 1; k < 64; k += 2) if (uidx_i[k] != 0) all0 = 0;
        g_is64 = all0;
    }
}

// ---------------- scatter into padded bins (no hist, no scan) ----------------
__global__ void k_scatter(const int4* __restrict__ rows4, const int4* __restrict__ cols4,
                          const float4* __restrict__ vals4) {
    int i = blockIdx.x * blockDim.x + threadIdx.x;   // over NNZ_E/4
    if (i >= NNZ_E / 4) return;
    int4   r = rows4[i];
    int4   c = cols4[i];
    float4 v = vals4[i];
    int2* pedge2 = (int2*)g_pedge4;
    // 4 independent atomic chains; stores follow their own atomic only
    int s0 = atomicAdd(&g_fill[r.x], 1);
    int s1 = atomicAdd(&g_fill[r.y], 1);
    int s2 = atomicAdd(&g_fill[r.z], 1);
    int s3 = atomicAdd(&g_fill[r.w], 1);
    pedge2[r.x * ROW_CAP + s0] = make_int2(c.x, __float_as_int(v.x));
    pedge2[r.y * ROW_CAP + s1] = make_int2(c.y, __float_as_int(v.y));
    pedge2[r.z * ROW_CAP + s2] = make_int2(c.z, __float_as_int(v.z));
    pedge2[r.w * ROW_CAP + s3] = make_int2(c.w, __float_as_int(v.w));
}

// ---------------- SpMM: quarter-warp per row, fp32 accum, int4 edges ---------
__device__ __forceinline__ void fma_edge(float2& a0, float2& a1, float2& a2, float2& a3,
                                         uint4 x, float v) {
    float2 f0 = __half22float2(*(half2*)&x.x);
    float2 f1 = __half22float2(*(half2*)&x.y);
    float2 f2 = __half22float2(*(half2*)&x.z);
    float2 f3 = __half22float2(*(half2*)&x.w);
    a0.x = fmaf(v, f0.x, a0.x); a0.y = fmaf(v, f0.y, a0.y);
    a1.x = fmaf(v, f1.x, a1.x); a1.y = fmaf(v, f1.y, a1.y);
    a2.x = fmaf(v, f2.x, a2.x); a2.y = fmaf(v, f2.y, a2.y);
    a3.x = fmaf(v, f3.x, a3.x); a3.y = fmaf(v, f3.y, a3.y);
}

__global__ void __launch_bounds__(256) k_spmm(int layer) {
    const uint4* __restrict__ src;
    uint4*       __restrict__ dst;
    if (layer == 0)      { src = g_e0; dst = g_e1; }
    else if (layer == 1) { src = g_e1; dst = g_e2; }
    else                 { src = g_e2; dst = g_e3; }

    int t    = blockIdx.x * blockDim.x + threadIdx.x;
    int w    = t >> 5;
    int lane = t & 31;
    int row  = w * 4 + (lane >> 3);       // 4 rows per warp (4 indep chains)
    int ql   = lane & 7;                  // lane within quarter-warp
    if (row >= N_NODES) return;

    const int4* __restrict__ ep4 = &g_pedge4[row * (ROW_CAP / 2)];
    int n = __ldg(&g_fill[row]);
    if (n > ROW_CAP) n = ROW_CAP;

    float2 a0 = {0.f, 0.f}, a1 = {0.f, 0.f}, a2 = {0.f, 0.f}, a3 = {0.f, 0.f};
    int j = 0;
    for (; j + 7 < n; j += 8) {
        // 4 evict-first LDG.128 loads carrying 8 edges
        int4 E0 = __ldcs(&ep4[(j >> 1)]);
        int4 E1 = __ldcs(&ep4[(j >> 1) + 1]);
        int4 E2 = __ldcs(&ep4[(j >> 1) + 2]);
        int4 E3 = __ldcs(&ep4[(j >> 1) + 3]);
        uint4 x0 = __ldg(&src[E0.x * 8 + ql]);
        uint4 x1 = __ldg(&src[E0.z * 8 + ql]);
        uint4 x2 = __ldg(&src[E1.x * 8 + ql]);
        uint4 x3 = __ldg(&src[E1.z * 8 + ql]);
        uint4 x4 = __ldg(&src[E2.x * 8 + ql]);
        uint4 x5 = __ldg(&src[E2.z * 8 + ql]);
        uint4 x6 = __ldg(&src[E3.x * 8 + ql]);
        uint4 x7 = __ldg(&src[E3.z * 8 + ql]);
        fma_edge(a0, a1, a2, a3, x0, __int_as_float(E0.y));
        fma_edge(a0, a1, a2, a3, x1, __int_as_float(E0.w));
        fma_edge(a0, a1, a2, a3, x2, __int_as_float(E1.y));
        fma_edge(a0, a1, a2, a3, x3, __int_as_float(E1.w));
        fma_edge(a0, a1, a2, a3, x4, __int_as_float(E2.y));
        fma_edge(a0, a1, a2, a3, x5, __int_as_float(E2.w));
        fma_edge(a0, a1, a2, a3, x6, __int_as_float(E3.y));
        fma_edge(a0, a1, a2, a3, x7, __int_as_float(E3.w));
    }
    const int2* __restrict__ ep2 = (const int2*)ep4;
    for (; j < n; j++) {
        int2 e = __ldcs(&ep2[j]);
        uint4 x = __ldg(&src[e.x * 8 + ql]);
        fma_edge(a0, a1, a2, a3, x, __int_as_float(e.y));
    }

    half2 h0 = __float22half2_rn(a0);
    half2 h1 = __float22half2_rn(a1);
    half2 h2 = __float22half2_rn(a2);
    half2 h3 = __float22half2_rn(a3);
    uint4 hv;
    hv.x = *(unsigned*)&h0; hv.y = *(unsigned*)&h1;
    hv.z = *(unsigned*)&h2; hv.w = *(unsigned*)&h3;
    dst[row * 8 + ql] = hv;
}

// ---------------- epilogue: sum 4 layer embeddings at gathered rows, dot -----
__global__ void k_dot(const float2* __restrict__ ue2, const float2* __restrict__ ie2,
                      const void* __restrict__ uidx_raw, const void* __restrict__ iidx_raw,
                      float* __restrict__ out) {
    int t    = blockIdx.x * blockDim.x + threadIdx.x;
    int w    = t >> 5;
    int lane = t & 31;
    if (w >= BATCH) return;

    long long u, it;
    if (g_is64) {
        u  = ((const long long*)uidx_raw)[w];
        it = ((const long long*)iidx_raw)[w];
    } else {
        u  = ((const int*)uidx_raw)[w];
        it = ((const int*)iidx_raw)[w];
    }

    size_t un = (size_t)u;                       // user node id
    size_t in = (size_t)N_USERS + (size_t)it;    // item node id

    // layer 0 straight from the inputs (exact fp32)
    float2 x = ue2[un * 32 + lane];
    float2 y = ie2[(size_t)it * 32 + lane];

    const unsigned* layers[3] = { (const unsigned*)g_e1, (const unsigned*)g_e2,
                                  (const unsigned*)g_e3 };
    #pragma unroll
    for (int l = 0; l < 3; l++) {
        unsigned hx = __ldg(&layers[l][un * 32 + lane]);
        unsigned hy = __ldg(&layers[l][in * 32 + lane]);
        float2 fx = __half22float2(*(half2*)&hx);
        float2 fy = __half22float2(*(half2*)&hy);
        x.x += fx.x; x.y += fx.y;
        y.x += fy.x; y.y += fy.y;
    }

    float p = x.x * y.x + x.y * y.y;
    #pragma unroll
    for (int off = 16; off; off >>= 1)
        p += __shfl_xor_sync(0xffffffffu, p, off);
    if (lane == 0) out[w] = p * (1.0f / 16.0f);   // (sum/4)·(sum/4)
}

// ---------------- launch ------------------------------------------------------
extern "C" void kernel_launch(void* const* d_in, const int* in_sizes, int n_in,
                              void* d_out, int out_size) {
    const float*  ue   = (const float*)d_in[0];
    const float*  ie   = (const float*)d_in[1];
    const int*    rows = (const int*)d_in[2];
    const int*    cols = (const int*)d_in[3];
    const float*  vals = (const float*)d_in[4];
    const void*   uidx = d_in[5];
    const void*   iidx = d_in[6];
    float* out = (float*)d_out;

    k_prep<<<(N_NODES * 32 + 255) / 256, 256>>>((const float2*)ue, (const float2*)ie,
                                                (const int*)uidx);
    k_scatter<<<(NNZ_E / 4 + 255) / 256, 256>>>((const int4*)rows, (const int4*)cols,
                                                (const float4*)vals);

    int spmm_blocks = ((N_NODES + 3) / 4 * 32 + 255) / 256;  // quarter-warp per row
    k_spmm<<<spmm_blocks, 256>>>(0);
    k_spmm<<<spmm_blocks, 256>>>(1);
    k_spmm<<<spmm_blocks, 256>>>(2);

    k_dot<<<BATCH * 32 / 256, 256>>>((const float2*)ue, (const float2*)ie, uidx, iidx, out);
}